// round 5
// baseline (speedup 1.0000x reference)
#include <cuda_runtime.h>

#define HF 64
#define WF 64
#define NPIX 4096
#define M_TOT 48
#define DCH 256

__device__ float g_A[M_TOT * NPIX];
__device__ float g_SA[M_TOT];
__device__ float g_u[M_TOT * DCH];

// ---------------------------------------------------------------------------
// K0: zero A and SA. 96 blocks x 512 threads, one float4 each.
// ---------------------------------------------------------------------------
__global__ void __launch_bounds__(512) k_zero() {
    int idx = blockIdx.x * 512 + threadIdx.x;           // 0..49151
    reinterpret_cast<float4*>(g_A)[idx] = make_float4(0.f, 0.f, 0.f, 0.f);
    if (idx < M_TOT) g_SA[idx] = 0.f;
}

// ---------------------------------------------------------------------------
// K1: flow downsample + bilinear weight scatter via global atomics.
// grid 192 (4 quarter-blocks per m), block 512, 2 dest pixels per thread.
// The 256->64 bilinear resize is an exact 2x2 average at rows/cols 4i+1,4i+2;
// one aligned float4 at column 4j covers both needed columns -> 4 vector
// loads per dest pixel (vs 8 scalar strided).
// ---------------------------------------------------------------------------
__global__ void __launch_bounds__(512) k_scatter(const float* __restrict__ pmot) {
    int m = blockIdx.x >> 2;
    int q = blockIdx.x & 3;
    const float* pm = pmot + (size_t)m * 2u * 65536u;
    float* Am = g_A + m * NPIX;
    const float inv = 1.0f / 4096.0f;
    float wsum = 0.f;

#pragma unroll
    for (int k = 0; k < 2; k++) {
        int p = q * 1024 + k * 512 + threadIdx.x;       // dest pixel 0..4095
        int i = p >> 6;
        int j = p & 63;

        const float4* ry1 = reinterpret_cast<const float4*>(pm + (4 * i + 1) * 256) + j;
        const float4* ry2 = reinterpret_cast<const float4*>(pm + (4 * i + 2) * 256) + j;
        float4 a0 = __ldg(ry1);
        float4 a1 = __ldg(ry2);
        float4 b0 = __ldg(ry1 + 16384);                 // +65536 floats = +16384 float4
        float4 b1 = __ldg(ry2 + 16384);

        float fy = (a0.y + a0.z + a1.y + a1.z) * 0.0625f;   // 2x2 avg * 0.25 scale
        float fx = (b0.y + b0.z + b1.y + b1.z) * 0.0625f;

        float y = (float)i + fy;
        float x = (float)j + fx;
        float y0f = floorf(y), x0f = floorf(x);
        float wy = y - y0f, wx = x - x0f;
        int y0 = (int)y0f, x0 = (int)x0f;
        int y1 = y0 + 1, x1 = x0 + 1;

        float w00 = (1.f - wy) * (1.f - wx) * inv;
        float w01 = (1.f - wy) * wx * inv;
        float w10 = wy * (1.f - wx) * inv;
        float w11 = wy * wx * inv;

        bool vy0 = (y0 >= 0) & (y0 < HF);
        bool vy1 = (y1 >= 0) & (y1 < HF);
        bool vx0 = (x0 >= 0) & (x0 < WF);
        bool vx1 = (x1 >= 0) & (x1 < WF);

        if (vy0 & vx0) { atomicAdd(Am + y0 * WF + x0, w00); wsum += w00; }
        if (vy0 & vx1) { atomicAdd(Am + y0 * WF + x1, w01); wsum += w01; }
        if (vy1 & vx0) { atomicAdd(Am + y1 * WF + x0, w10); wsum += w10; }
        if (vy1 & vx1) { atomicAdd(Am + y1 * WF + x1, w11); wsum += w11; }
    }

    // block-level SA reduction -> single global atomic per block
    __shared__ float partial[16];
    int warp = threadIdx.x >> 5, lane = threadIdx.x & 31;
#pragma unroll
    for (int off = 16; off; off >>= 1)
        wsum += __shfl_down_sync(0xffffffffu, wsum, off);
    if (lane == 0) partial[warp] = wsum;
    __syncthreads();
    if (warp == 0) {
        float t = (lane < 16) ? partial[lane] : 0.f;
#pragma unroll
        for (int off = 8; off; off >>= 1)
            t += __shfl_down_sync(0xffffffffu, t, off);
        if (lane == 0) atomicAdd(&g_SA[m], t);
    }
}

// ---------------------------------------------------------------------------
// K2: u[m][c] = dot(A[m], i_features[gf][c]) for the 3 m's sharing gf.
// grid (16 gf, 32 ctiles of 8 channels), block 256. A weights in registers,
// double-buffered float4 feature loads, warp-shuffle reduce.
// ---------------------------------------------------------------------------
__global__ void __launch_bounds__(256) k_reduce(const float* __restrict__ feat) {
    int gf = blockIdx.x;            // 0..15 == b*4+g
    int b = gf >> 2, g = gf & 3;
    int m0 = b * 12 + g * 3;

    const float4* A4 = reinterpret_cast<const float4*>(g_A);
    float4 a[3][4];
#pragma unroll
    for (int r = 0; r < 3; r++)
#pragma unroll
        for (int k = 0; k < 4; k++)
            a[r][k] = A4[(m0 + r) * 1024 + k * 256 + threadIdx.x];

    __shared__ float red[8][8][3];
    int warp = threadIdx.x >> 5;
    int lane = threadIdx.x & 31;

    const float4* F4 = reinterpret_cast<const float4*>(feat)
                     + (size_t)gf * DCH * 1024
                     + (size_t)blockIdx.y * 8 * 1024;

    float4 cur[4], nxt[4];
#pragma unroll
    for (int k = 0; k < 4; k++) cur[k] = F4[k * 256 + threadIdx.x];

#pragma unroll
    for (int ch = 0; ch < 8; ch++) {
        if (ch < 7) {
#pragma unroll
            for (int k = 0; k < 4; k++)
                nxt[k] = F4[(ch + 1) * 1024 + k * 256 + threadIdx.x];
        }
        float acc0 = 0.f, acc1 = 0.f, acc2 = 0.f;
#pragma unroll
        for (int k = 0; k < 4; k++) {
            float4 f = cur[k];
            acc0 += a[0][k].x * f.x + a[0][k].y * f.y + a[0][k].z * f.z + a[0][k].w * f.w;
            acc1 += a[1][k].x * f.x + a[1][k].y * f.y + a[1][k].z * f.z + a[1][k].w * f.w;
            acc2 += a[2][k].x * f.x + a[2][k].y * f.y + a[2][k].z * f.z + a[2][k].w * f.w;
        }
#pragma unroll
        for (int off = 16; off; off >>= 1) {
            acc0 += __shfl_down_sync(0xffffffffu, acc0, off);
            acc1 += __shfl_down_sync(0xffffffffu, acc1, off);
            acc2 += __shfl_down_sync(0xffffffffu, acc2, off);
        }
        if (lane == 0) {
            red[ch][warp][0] = acc0;
            red[ch][warp][1] = acc1;
            red[ch][warp][2] = acc2;
        }
        if (ch < 7) {
#pragma unroll
            for (int k = 0; k < 4; k++) cur[k] = nxt[k];
        }
    }
    __syncthreads();

    if (threadIdx.x < 24) {
        int ch = threadIdx.x / 3;
        int r  = threadIdx.x % 3;
        float s = 0.f;
#pragma unroll
        for (int w = 0; w < 8; w++) s += red[ch][w][r];
        g_u[(m0 + r) * DCH + blockIdx.y * 8 + ch] = s;
    }
}

// ---------------------------------------------------------------------------
// K3: fused double GEMV per m. 48 blocks x 1024 threads (32 warps).
//   s[c]  = b_emb[c]*SA[m] + dot(W_emb[c,:], u[m,:])
//   out[o]= b_dc[o]        + dot(W_dc[o,:],  s[:])
// ---------------------------------------------------------------------------
__global__ void __launch_bounds__(1024) k_final(
    const float* __restrict__ W_emb, const float* __restrict__ b_emb,
    const float* __restrict__ W_dc,  const float* __restrict__ b_dc,
    float* __restrict__ out)
{
    int m = blockIdx.x;
    int tid = threadIdx.x;
    int warp = tid >> 5, lane = tid & 31;

    __shared__ float ush[DCH];
    __shared__ float ssh[DCH];

    if (tid < DCH) ush[tid] = g_u[m * DCH + tid];
    __syncthreads();

    float sa = g_SA[m];

#pragma unroll
    for (int i = 0; i < 8; i++) {
        int c = warp * 8 + i;
        const float* Wr = W_emb + c * DCH;
        float acc = 0.f;
#pragma unroll
        for (int k = 0; k < 8; k++)
            acc += Wr[k * 32 + lane] * ush[k * 32 + lane];
#pragma unroll
        for (int off = 16; off; off >>= 1)
            acc += __shfl_down_sync(0xffffffffu, acc, off);
        if (lane == 0) ssh[c] = acc + b_emb[c] * sa;
    }
    __syncthreads();

#pragma unroll
    for (int i = 0; i < 8; i++) {
        int o = warp * 8 + i;
        const float* Wr = W_dc + o * DCH;
        float acc = 0.f;
#pragma unroll
        for (int k = 0; k < 8; k++)
            acc += Wr[k * 32 + lane] * ssh[k * 32 + lane];
#pragma unroll
        for (int off = 16; off; off >>= 1)
            acc += __shfl_down_sync(0xffffffffu, acc, off);
        if (lane == 0) out[m * DCH + o] = acc + b_dc[o];
    }
}

// ---------------------------------------------------------------------------
// inputs (metadata order): imgs, i_features, p_motions, W_emb, b_emb, W_dc, b_dc
// output: float32 [4,4,3,256] = 12288 elements
// ---------------------------------------------------------------------------
extern "C" void kernel_launch(void* const* d_in, const int* in_sizes, int n_in,
                              void* d_out, int out_size) {
    const float* i_features = (const float*)d_in[1];
    const float* p_motions  = (const float*)d_in[2];
    const float* W_emb      = (const float*)d_in[3];
    const float* b_emb      = (const float*)d_in[4];
    const float* W_dc       = (const float*)d_in[5];
    const float* b_dc       = (const float*)d_in[6];
    float* out = (float*)d_out;

    k_zero<<<96, 512>>>();
    k_scatter<<<192, 512>>>(p_motions);
    k_reduce<<<dim3(16, 32), 256>>>(i_features);
    k_final<<<48, 1024>>>(W_emb, b_emb, W_dc, b_dc, out);
}

// round 6
// speedup vs baseline: 1.0595x; 1.0595x over previous
#include <cuda_runtime.h>

#define HF 64
#define WF 64
#define NPIX 4096
#define M_TOT 48
#define DCH 256

__device__ float g_A[M_TOT * NPIX];
__device__ float g_SA[M_TOT];
__device__ float g_u[M_TOT * DCH];
__device__ float g_WcT[DCH * DCH];    // WcombT[c][o] = sum_k W_dc[o,k]*W_emb[k,c]
__device__ float g_bcomb[DCH];        // bcomb[o] = sum_k W_dc[o,k]*b_emb[k]

// ---------------------------------------------------------------------------
// K_gemm: Wcomb = W_dc x W_emb (256x256x256), stored TRANSPOSED (c-major) so
// the final GEMV reads it coalesced. Also bcomb = W_dc x b_emb, and zeroes
// d_out for the atomic accumulation in k_out. Input-independent -> runs first.
// grid (8 o-tiles, 8 c-tiles) = 64 blocks x 256 threads; 32x32 tiles, K=256
// in 8 chunks of 32 staged in shared.
// ---------------------------------------------------------------------------
__global__ void __launch_bounds__(256) k_gemm(
    const float* __restrict__ W_emb, const float* __restrict__ b_emb,
    const float* __restrict__ W_dc,  float* __restrict__ out)
{
    int tid = threadIdx.x;
    int o0 = blockIdx.x * 32;
    int c0 = blockIdx.y * 32;

    __shared__ float Adc[32][33];    // [o_local][k_local]
    __shared__ float Bem[32][33];    // [k_local][c_local]
    __shared__ float bsh[32];

    // zero the output buffer (12288 floats / 64 blocks = 192 each)
    {
        int blin = blockIdx.y * 8 + blockIdx.x;
        if (tid < 192) out[blin * 192 + tid] = 0.f;
    }

    int o_l = tid & 31;
    int c_l0 = (tid >> 5) * 4;
    float acc[4] = {0.f, 0.f, 0.f, 0.f};
    float bacc = 0.f;

    for (int kc = 0; kc < 8; kc++) {
        int k0 = kc * 32;
        __syncthreads();
#pragma unroll
        for (int e = 0; e < 4; e++) {
            int idx = e * 256 + tid;
            int r = idx >> 5, cc = idx & 31;
            Adc[r][cc] = W_dc[(o0 + r) * DCH + k0 + cc];
            Bem[r][cc] = W_emb[(k0 + r) * DCH + c0 + cc];
        }
        if (blockIdx.y == 0 && tid < 32) bsh[tid] = b_emb[k0 + tid];
        __syncthreads();

#pragma unroll
        for (int kk = 0; kk < 32; kk++) {
            float a = Adc[o_l][kk];
#pragma unroll
            for (int i = 0; i < 4; i++)
                acc[i] += a * Bem[kk][c_l0 + i];
        }
        if (blockIdx.y == 0 && tid < 32) {
#pragma unroll
            for (int kk = 0; kk < 32; kk++)
                bacc += Adc[tid][kk] * bsh[kk];
        }
    }

#pragma unroll
    for (int i = 0; i < 4; i++)
        g_WcT[(c0 + c_l0 + i) * DCH + o0 + o_l] = acc[i];   // coalesced over o_l
    if (blockIdx.y == 0 && tid < 32) g_bcomb[o0 + tid] = bacc;
}

// ---------------------------------------------------------------------------
// K_scatter: per-m flow downsample + bilinear weight scatter in shared.
// One block per m, 1024 threads, 4 dest pixels/thread. The 256->64 bilinear
// resize is an exact 2x2 average at rows/cols 4i+1,4i+2; one aligned float4
// at column index j covers cols 4j..4j+3 -> 4 vector loads per pixel.
// SA = tile sum during copy-out.
// ---------------------------------------------------------------------------
__global__ void __launch_bounds__(1024) k_scatter(const float* __restrict__ pmot) {
    int m = blockIdx.x;
    int tid = threadIdx.x;
    const float4* pm4 = reinterpret_cast<const float4*>(pmot + (size_t)m * 2u * 65536u);

    __shared__ float Ash[NPIX];
    __shared__ float partial[32];

#pragma unroll
    for (int k = 0; k < 4; k++) Ash[k * 1024 + tid] = 0.f;
    __syncthreads();

    const float inv = 1.0f / 4096.0f;
#pragma unroll
    for (int k = 0; k < 4; k++) {
        int p = k * 1024 + tid;      // dest pixel 0..4095
        int i = p >> 6;
        int j = p & 63;

        const float4* ry1 = pm4 + (4 * i + 1) * 64 + j;
        const float4* ry2 = pm4 + (4 * i + 2) * 64 + j;
        float4 a0 = __ldg(ry1);
        float4 a1 = __ldg(ry2);
        float4 b0 = __ldg(ry1 + 16384);     // x-flow channel (+65536 floats)
        float4 b1 = __ldg(ry2 + 16384);

        float fy = (a0.y + a0.z + a1.y + a1.z) * 0.0625f;   // 2x2 avg * 0.25
        float fx = (b0.y + b0.z + b1.y + b1.z) * 0.0625f;

        float y = (float)i + fy;
        float x = (float)j + fx;
        float y0f = floorf(y), x0f = floorf(x);
        float wy = y - y0f, wx = x - x0f;
        int y0 = (int)y0f, x0 = (int)x0f;
        int y1 = y0 + 1, x1 = x0 + 1;

        float w00 = (1.f - wy) * (1.f - wx) * inv;
        float w01 = (1.f - wy) * wx * inv;
        float w10 = wy * (1.f - wx) * inv;
        float w11 = wy * wx * inv;

        bool vy0 = (y0 >= 0) & (y0 < HF);
        bool vy1 = (y1 >= 0) & (y1 < HF);
        bool vx0 = (x0 >= 0) & (x0 < WF);
        bool vx1 = (x1 >= 0) & (x1 < WF);

        if (vy0 & vx0) atomicAdd(&Ash[y0 * WF + x0], w00);
        if (vy0 & vx1) atomicAdd(&Ash[y0 * WF + x1], w01);
        if (vy1 & vx0) atomicAdd(&Ash[y1 * WF + x0], w10);
        if (vy1 & vx1) atomicAdd(&Ash[y1 * WF + x1], w11);
    }
    __syncthreads();

    // copy out + SA = sum(Ash)
    float4 v = reinterpret_cast<const float4*>(Ash)[tid];
    reinterpret_cast<float4*>(g_A)[m * 1024 + tid] = v;
    float s = v.x + v.y + v.z + v.w;
#pragma unroll
    for (int off = 16; off; off >>= 1)
        s += __shfl_down_sync(0xffffffffu, s, off);
    int warp = tid >> 5, lane = tid & 31;
    if (lane == 0) partial[warp] = s;
    __syncthreads();
    if (warp == 0) {
        float t = partial[lane];
#pragma unroll
        for (int off = 16; off; off >>= 1)
            t += __shfl_down_sync(0xffffffffu, t, off);
        if (lane == 0) g_SA[m] = t;
    }
}

// ---------------------------------------------------------------------------
// K_reduce: u[m][c] = dot(A[m], i_features[gf][c]) for the 3 m's sharing gf.
// grid (16 gf, 32 ctiles of 8 channels), block 256.
// ---------------------------------------------------------------------------
__global__ void __launch_bounds__(256) k_reduce(const float* __restrict__ feat) {
    int gf = blockIdx.x;            // 0..15 == b*4+g
    int b = gf >> 2, g = gf & 3;
    int m0 = b * 12 + g * 3;

    const float4* A4 = reinterpret_cast<const float4*>(g_A);
    float4 a[3][4];
#pragma unroll
    for (int r = 0; r < 3; r++)
#pragma unroll
        for (int k = 0; k < 4; k++)
            a[r][k] = A4[(m0 + r) * 1024 + k * 256 + threadIdx.x];

    __shared__ float red[8][8][3];
    int warp = threadIdx.x >> 5;
    int lane = threadIdx.x & 31;

    const float4* F4 = reinterpret_cast<const float4*>(feat)
                     + (size_t)gf * DCH * 1024
                     + (size_t)blockIdx.y * 8 * 1024;

    float4 cur[4], nxt[4];
#pragma unroll
    for (int k = 0; k < 4; k++) cur[k] = F4[k * 256 + threadIdx.x];

#pragma unroll
    for (int ch = 0; ch < 8; ch++) {
        if (ch < 7) {
#pragma unroll
            for (int k = 0; k < 4; k++)
                nxt[k] = F4[(ch + 1) * 1024 + k * 256 + threadIdx.x];
        }
        float acc0 = 0.f, acc1 = 0.f, acc2 = 0.f;
#pragma unroll
        for (int k = 0; k < 4; k++) {
            float4 f = cur[k];
            acc0 += a[0][k].x * f.x + a[0][k].y * f.y + a[0][k].z * f.z + a[0][k].w * f.w;
            acc1 += a[1][k].x * f.x + a[1][k].y * f.y + a[1][k].z * f.z + a[1][k].w * f.w;
            acc2 += a[2][k].x * f.x + a[2][k].y * f.y + a[2][k].z * f.z + a[2][k].w * f.w;
        }
#pragma unroll
        for (int off = 16; off; off >>= 1) {
            acc0 += __shfl_down_sync(0xffffffffu, acc0, off);
            acc1 += __shfl_down_sync(0xffffffffu, acc1, off);
            acc2 += __shfl_down_sync(0xffffffffu, acc2, off);
        }
        if (lane == 0) {
            red[ch][warp][0] = acc0;
            red[ch][warp][1] = acc1;
            red[ch][warp][2] = acc2;
        }
        if (ch < 7) {
#pragma unroll
            for (int k = 0; k < 4; k++) cur[k] = nxt[k];
        }
    }
    __syncthreads();

    if (threadIdx.x < 24) {
        int ch = threadIdx.x / 3;
        int r  = threadIdx.x % 3;
        float s = 0.f;
#pragma unroll
        for (int w = 0; w < 8; w++) s += red[ch][w][r];
        g_u[(m0 + r) * DCH + blockIdx.y * 8 + ch] = s;
    }
}

// ---------------------------------------------------------------------------
// K_out: out[m][o] += sum_{c in chunk} WcT[c][o]*u[m][c]  (+ bias on chunk 0)
// grid (48 m, 4 k-chunks of 64) = 192 blocks x 256 threads, thread = o.
// WcT loads coalesced across threads; K unrolled for MLP; atomic accumulate
// into the pre-zeroed out buffer.
// ---------------------------------------------------------------------------
__global__ void __launch_bounds__(256) k_out(
    const float* __restrict__ b_dc, float* __restrict__ out)
{
    int m = blockIdx.x;
    int q = blockIdx.y;
    int tid = threadIdx.x;

    __shared__ float usm[64];
    if (tid < 64) usm[tid] = g_u[m * DCH + q * 64 + tid];
    __syncthreads();

    const float* Wp = g_WcT + (q * 64) * DCH + tid;
    float acc = 0.f;
#pragma unroll 16
    for (int c = 0; c < 64; c++)
        acc += Wp[c * DCH] * usm[c];

    if (q == 0)
        acc += g_SA[m] * g_bcomb[tid] + b_dc[tid];
    atomicAdd(&out[m * DCH + tid], acc);
}

// ---------------------------------------------------------------------------
// inputs (metadata order): imgs, i_features, p_motions, W_emb, b_emb, W_dc, b_dc
// output: float32 [4,4,3,256] = 12288 elements
// ---------------------------------------------------------------------------
extern "C" void kernel_launch(void* const* d_in, const int* in_sizes, int n_in,
                              void* d_out, int out_size) {
    const float* i_features = (const float*)d_in[1];
    const float* p_motions  = (const float*)d_in[2];
    const float* W_emb      = (const float*)d_in[3];
    const float* b_emb      = (const float*)d_in[4];
    const float* W_dc       = (const float*)d_in[5];
    const float* b_dc       = (const float*)d_in[6];
    float* out = (float*)d_out;

    k_gemm<<<dim3(8, 8), 256>>>(W_emb, b_emb, W_dc, out);   // input-independent + zeroes out
    k_scatter<<<48, 1024>>>(p_motions);
    k_reduce<<<dim3(16, 32), 256>>>(i_features);
    k_out<<<dim3(48, 4), 256>>>(b_dc, out);
}

// round 7
// speedup vs baseline: 1.2895x; 1.2171x over previous
#include <cuda_runtime.h>

#define HF 64
#define WF 64
#define NPIX 4096
#define M_TOT 48
#define DCH 256

__device__ float g_A[M_TOT * NPIX];
__device__ float g_SA[M_TOT];
__device__ float g_WcT[DCH * DCH];    // WcT[c][o] = sum_k W_dc[o,k]*W_emb[k,c]
__device__ float g_bcomb[DCH];        // bcomb[o] = sum_k W_dc[o,k]*b_emb[k]

// ---------------------------------------------------------------------------
// K_gemm: Wcomb = W_dc x W_emb (256^3), stored transposed (c-major) for
// coalesced epilogue reads. One thread per output element, 16x16 tiles,
// full K=256 staged in shared (single stage, no k-loop barriers).
// Also computes bcomb and zeroes d_out. Input-independent -> first.
// ---------------------------------------------------------------------------
__global__ void __launch_bounds__(256) k_gemm(
    const float* __restrict__ W_emb, const float* __restrict__ b_emb,
    const float* __restrict__ W_dc,  float* __restrict__ out)
{
    int tid = threadIdx.x;
    int o0 = blockIdx.x * 16;
    int c0 = blockIdx.y * 16;

    __shared__ float sA[16][257];    // W_dc rows   [o_local][k]
    __shared__ float sB[256][17];    // W_emb       [k][c_local]
    __shared__ float bsh[256];

    // zero the output buffer (first 48 blocks cover 48*256 floats)
    {
        int blin = blockIdx.y * 16 + blockIdx.x;
        if (blin < M_TOT) out[blin * DCH + tid] = 0.f;
    }

#pragma unroll
    for (int e = 0; e < 16; e++) {
        int idx = e * 256 + tid;
        sA[idx >> 8][idx & 255] = W_dc[(o0 + (idx >> 8)) * DCH + (idx & 255)];
        sB[idx >> 4][idx & 15]  = W_emb[(idx >> 4) * DCH + c0 + (idx & 15)];
    }
    if (blockIdx.y == 0) bsh[tid] = b_emb[tid];
    __syncthreads();

    int tx = tid & 15;        // o_local
    int ty = tid >> 4;        // c_local
    float acc = 0.f;
#pragma unroll 8
    for (int k = 0; k < 256; k++)
        acc += sA[tx][k] * sB[k][ty];
    g_WcT[(c0 + ty) * DCH + o0 + tx] = acc;

    if (blockIdx.y == 0 && tid < 16) {
        float bacc = 0.f;
#pragma unroll 8
        for (int k = 0; k < 256; k++)
            bacc += sA[tid][k] * bsh[k];
        g_bcomb[o0 + tid] = bacc;
    }
}

// ---------------------------------------------------------------------------
// K_scatter: per-m flow downsample + bilinear weight scatter in shared.
// One block per m, 1024 threads, 4 dest pixels/thread. 256->64 bilinear
// resize == exact 2x2 average at rows/cols 4i+1,4i+2; one aligned float4
// covers both needed columns. SA = tile sum during copy-out.
// ---------------------------------------------------------------------------
__global__ void __launch_bounds__(1024) k_scatter(const float* __restrict__ pmot) {
    int m = blockIdx.x;
    int tid = threadIdx.x;
    const float4* pm4 = reinterpret_cast<const float4*>(pmot + (size_t)m * 2u * 65536u);

    __shared__ float Ash[NPIX];
    __shared__ float partial[32];

#pragma unroll
    for (int k = 0; k < 4; k++) Ash[k * 1024 + tid] = 0.f;
    __syncthreads();

    const float inv = 1.0f / 4096.0f;
#pragma unroll
    for (int k = 0; k < 4; k++) {
        int p = k * 1024 + tid;      // dest pixel 0..4095
        int i = p >> 6;
        int j = p & 63;

        const float4* ry1 = pm4 + (4 * i + 1) * 64 + j;
        const float4* ry2 = pm4 + (4 * i + 2) * 64 + j;
        float4 a0 = __ldg(ry1);
        float4 a1 = __ldg(ry2);
        float4 b0 = __ldg(ry1 + 16384);     // x-flow channel
        float4 b1 = __ldg(ry2 + 16384);

        float fy = (a0.y + a0.z + a1.y + a1.z) * 0.0625f;   // 2x2 avg * 0.25
        float fx = (b0.y + b0.z + b1.y + b1.z) * 0.0625f;

        float y = (float)i + fy;
        float x = (float)j + fx;
        float y0f = floorf(y), x0f = floorf(x);
        float wy = y - y0f, wx = x - x0f;
        int y0 = (int)y0f, x0 = (int)x0f;
        int y1 = y0 + 1, x1 = x0 + 1;

        float w00 = (1.f - wy) * (1.f - wx) * inv;
        float w01 = (1.f - wy) * wx * inv;
        float w10 = wy * (1.f - wx) * inv;
        float w11 = wy * wx * inv;

        bool vy0 = (y0 >= 0) & (y0 < HF);
        bool vy1 = (y1 >= 0) & (y1 < HF);
        bool vx0 = (x0 >= 0) & (x0 < WF);
        bool vx1 = (x1 >= 0) & (x1 < WF);

        if (vy0 & vx0) atomicAdd(&Ash[y0 * WF + x0], w00);
        if (vy0 & vx1) atomicAdd(&Ash[y0 * WF + x1], w01);
        if (vy1 & vx0) atomicAdd(&Ash[y1 * WF + x0], w10);
        if (vy1 & vx1) atomicAdd(&Ash[y1 * WF + x1], w11);
    }
    __syncthreads();

    float4 v = reinterpret_cast<const float4*>(Ash)[tid];
    reinterpret_cast<float4*>(g_A)[m * 1024 + tid] = v;
    float s = v.x + v.y + v.z + v.w;
#pragma unroll
    for (int off = 16; off; off >>= 1)
        s += __shfl_down_sync(0xffffffffu, s, off);
    int warp = tid >> 5, lane = tid & 31;
    if (lane == 0) partial[warp] = s;
    __syncthreads();
    if (warp == 0) {
        float t = partial[lane];
#pragma unroll
        for (int off = 16; off; off >>= 1)
            t += __shfl_down_sync(0xffffffffu, t, off);
        if (lane == 0) g_SA[m] = t;
    }
}

// ---------------------------------------------------------------------------
// K_reduce: partial u for 8 channels x 3 m's, then Wcomb epilogue:
//   out[m][o] += sum_ch WcT[c0+ch][o] * u_part[m][ch]   (+ bias on ctile 0)
// grid (16 gf, 32 ctiles), block 256. Deletes k_out and g_u entirely.
// ---------------------------------------------------------------------------
__global__ void __launch_bounds__(256) k_reduce(
    const float* __restrict__ feat, const float* __restrict__ b_dc,
    float* __restrict__ out)
{
    int gf = blockIdx.x;            // 0..15 == b*4+g
    int b = gf >> 2, g = gf & 3;
    int m0 = b * 12 + g * 3;

    const float4* A4 = reinterpret_cast<const float4*>(g_A);
    float4 a[3][4];
#pragma unroll
    for (int r = 0; r < 3; r++)
#pragma unroll
        for (int k = 0; k < 4; k++)
            a[r][k] = A4[(m0 + r) * 1024 + k * 256 + threadIdx.x];

    __shared__ float red[8][8][3];
    __shared__ float sacc[3][8];
    int warp = threadIdx.x >> 5;
    int lane = threadIdx.x & 31;

    const float4* F4 = reinterpret_cast<const float4*>(feat)
                     + (size_t)gf * DCH * 1024
                     + (size_t)blockIdx.y * 8 * 1024;

    float4 cur[4], nxt[4];
#pragma unroll
    for (int k = 0; k < 4; k++) cur[k] = F4[k * 256 + threadIdx.x];

#pragma unroll
    for (int ch = 0; ch < 8; ch++) {
        if (ch < 7) {
#pragma unroll
            for (int k = 0; k < 4; k++)
                nxt[k] = F4[(ch + 1) * 1024 + k * 256 + threadIdx.x];
        }
        float acc0 = 0.f, acc1 = 0.f, acc2 = 0.f;
#pragma unroll
        for (int k = 0; k < 4; k++) {
            float4 f = cur[k];
            acc0 += a[0][k].x * f.x + a[0][k].y * f.y + a[0][k].z * f.z + a[0][k].w * f.w;
            acc1 += a[1][k].x * f.x + a[1][k].y * f.y + a[1][k].z * f.z + a[1][k].w * f.w;
            acc2 += a[2][k].x * f.x + a[2][k].y * f.y + a[2][k].z * f.z + a[2][k].w * f.w;
        }
#pragma unroll
        for (int off = 16; off; off >>= 1) {
            acc0 += __shfl_down_sync(0xffffffffu, acc0, off);
            acc1 += __shfl_down_sync(0xffffffffu, acc1, off);
            acc2 += __shfl_down_sync(0xffffffffu, acc2, off);
        }
        if (lane == 0) {
            red[ch][warp][0] = acc0;
            red[ch][warp][1] = acc1;
            red[ch][warp][2] = acc2;
        }
        if (ch < 7) {
#pragma unroll
            for (int k = 0; k < 4; k++) cur[k] = nxt[k];
        }
    }
    __syncthreads();

    if (threadIdx.x < 24) {
        int ch = threadIdx.x / 3;
        int r  = threadIdx.x % 3;
        float s = 0.f;
#pragma unroll
        for (int w = 0; w < 8; w++) s += red[ch][w][r];
        sacc[r][ch] = s;
    }
    __syncthreads();

    // Wcomb epilogue: thread = output channel o
    int o = threadIdx.x;
    int c0 = blockIdx.y * 8;
    float v0 = 0.f, v1 = 0.f, v2 = 0.f;
#pragma unroll
    for (int ch = 0; ch < 8; ch++) {
        float wv = g_WcT[(c0 + ch) * DCH + o];
        v0 += wv * sacc[0][ch];
        v1 += wv * sacc[1][ch];
        v2 += wv * sacc[2][ch];
    }
    if (blockIdx.y == 0) {
        float bc = g_bcomb[o];
        float bd = b_dc[o];
        v0 += g_SA[m0 + 0] * bc + bd;
        v1 += g_SA[m0 + 1] * bc + bd;
        v2 += g_SA[m0 + 2] * bc + bd;
    }
    atomicAdd(&out[(m0 + 0) * DCH + o], v0);
    atomicAdd(&out[(m0 + 1) * DCH + o], v1);
    atomicAdd(&out[(m0 + 2) * DCH + o], v2);
}

// ---------------------------------------------------------------------------
// inputs (metadata order): imgs, i_features, p_motions, W_emb, b_emb, W_dc, b_dc
// output: float32 [4,4,3,256] = 12288 elements
// ---------------------------------------------------------------------------
extern "C" void kernel_launch(void* const* d_in, const int* in_sizes, int n_in,
                              void* d_out, int out_size) {
    const float* i_features = (const float*)d_in[1];
    const float* p_motions  = (const float*)d_in[2];
    const float* W_emb      = (const float*)d_in[3];
    const float* b_emb      = (const float*)d_in[4];
    const float* W_dc       = (const float*)d_in[5];
    const float* b_dc       = (const float*)d_in[6];
    float* out = (float*)d_out;

    k_gemm<<<dim3(16, 16), 256>>>(W_emb, b_emb, W_dc, out);  // zeroes out too
    k_scatter<<<48, 1024>>>(p_motions);
    k_reduce<<<dim3(16, 32), 256>>>(i_features, b_dc, out);
}

// round 8
// speedup vs baseline: 1.3868x; 1.0755x over previous
#include <cuda_runtime.h>

#define HF 64
#define WF 64
#define NPIX 4096
#define M_TOT 48
#define DCH 256

__device__ float g_A[M_TOT * NPIX];
__device__ float g_SA[M_TOT];
__device__ float g_WcT[DCH * DCH];    // WcT[c][o] = sum_k W_dc[o,k]*W_emb[k,c]
__device__ float g_bcomb[DCH];        // bcomb[o] = sum_k W_dc[o,k]*b_emb[k]

// shared-memory union for the merged front kernel
struct GemmSmem {
    float sA[32][268];   // W_dc rows, k-major, padded (bank-conflict-free f4)
    float sB[16][268];   // W_emb cols, k-major
    float bsh[256];
};
struct ScatSmem {
    float Ash[NPIX];
    float partial[16];
};
#define FRONT_SMEM 53248   // >= sizeof(GemmSmem) = 52480

// ---------------------------------------------------------------------------
// K_front: 176 blocks x 512 threads.
//   blocks 0..127  : Wcomb GEMM (32x16 tiles), bcomb, zero d_out
//   blocks 128..175: per-m flow downsample + bilinear weight scatter
// The two halves are independent; merging gives free concurrency.
// ---------------------------------------------------------------------------
__global__ void __launch_bounds__(512) k_front(
    const float* __restrict__ W_emb, const float* __restrict__ b_emb,
    const float* __restrict__ W_dc,  const float* __restrict__ pmot,
    float* __restrict__ out)
{
    extern __shared__ char smem_raw[];
    int tid = threadIdx.x;

    if (blockIdx.x < 128) {
        // ------------------- GEMM half -------------------
        GemmSmem& S = *reinterpret_cast<GemmSmem*>(smem_raw);
        int bo = blockIdx.x & 7;      // 8 o-tiles of 32
        int bc = blockIdx.x >> 3;     // 16 c-tiles of 16
        int o0 = bo * 32, c0 = bc * 16;

        if (blockIdx.x < M_TOT && tid < 256) out[blockIdx.x * DCH + tid] = 0.f;

#pragma unroll
        for (int e = 0; e < 16; e++) {           // sA: 32x256, coalesced reads
            int idx = e * 512 + tid;
            int o = idx >> 8, k = idx & 255;
            S.sA[o][k] = W_dc[(o0 + o) * DCH + k];
        }
#pragma unroll
        for (int e = 0; e < 8; e++) {            // sB: 16x256 (transpose load)
            int idx = e * 512 + tid;
            int c = idx & 15, k = idx >> 4;
            S.sB[c][k] = W_emb[k * DCH + c0 + c];
        }
        if (bc == 0 && tid < 256) S.bsh[tid] = b_emb[tid];
        __syncthreads();

        int o_l = tid & 31, c_l = tid >> 5;
        const float4* a4 = reinterpret_cast<const float4*>(S.sA[o_l]);
        const float4* b4 = reinterpret_cast<const float4*>(S.sB[c_l]);
        float acc = 0.f;
#pragma unroll 8
        for (int k4 = 0; k4 < 64; k4++) {
            float4 a = a4[k4], b = b4[k4];
            acc += a.x * b.x + a.y * b.y + a.z * b.z + a.w * b.w;
        }
        g_WcT[(c0 + c_l) * DCH + o0 + o_l] = acc;

        if (bc == 0 && tid < 32) {
            const float4* aa = reinterpret_cast<const float4*>(S.sA[tid]);
            const float4* bb = reinterpret_cast<const float4*>(S.bsh);
            float bacc = 0.f;
#pragma unroll 8
            for (int k4 = 0; k4 < 64; k4++) {
                float4 a = aa[k4], b = bb[k4];
                bacc += a.x * b.x + a.y * b.y + a.z * b.z + a.w * b.w;
            }
            g_bcomb[o0 + tid] = bacc;
        }
    } else {
        // ------------------- scatter half -------------------
        ScatSmem& S = *reinterpret_cast<ScatSmem*>(smem_raw);
        int m = blockIdx.x - 128;
        const float4* pm4 = reinterpret_cast<const float4*>(pmot + (size_t)m * 2u * 65536u);

#pragma unroll
        for (int k = 0; k < 8; k++) S.Ash[k * 512 + tid] = 0.f;
        __syncthreads();

        const float inv = 1.0f / 4096.0f;
#pragma unroll
        for (int k = 0; k < 8; k++) {
            int p = k * 512 + tid;        // dest pixel 0..4095
            int i = p >> 6;
            int j = p & 63;

            const float4* ry1 = pm4 + (4 * i + 1) * 64 + j;
            const float4* ry2 = pm4 + (4 * i + 2) * 64 + j;
            float4 a0 = __ldg(ry1);
            float4 a1 = __ldg(ry2);
            float4 b0 = __ldg(ry1 + 16384);   // x-flow channel
            float4 b1 = __ldg(ry2 + 16384);

            float fy = (a0.y + a0.z + a1.y + a1.z) * 0.0625f;  // 2x2 avg * 0.25
            float fx = (b0.y + b0.z + b1.y + b1.z) * 0.0625f;

            float y = (float)i + fy;
            float x = (float)j + fx;
            float y0f = floorf(y), x0f = floorf(x);
            float wy = y - y0f, wx = x - x0f;
            int y0 = (int)y0f, x0 = (int)x0f;
            int y1 = y0 + 1, x1 = x0 + 1;

            float w00 = (1.f - wy) * (1.f - wx) * inv;
            float w01 = (1.f - wy) * wx * inv;
            float w10 = wy * (1.f - wx) * inv;
            float w11 = wy * wx * inv;

            bool vy0 = (y0 >= 0) & (y0 < HF);
            bool vy1 = (y1 >= 0) & (y1 < HF);
            bool vx0 = (x0 >= 0) & (x0 < WF);
            bool vx1 = (x1 >= 0) & (x1 < WF);

            if (vy0 & vx0) atomicAdd(&S.Ash[y0 * WF + x0], w00);
            if (vy0 & vx1) atomicAdd(&S.Ash[y0 * WF + x1], w01);
            if (vy1 & vx0) atomicAdd(&S.Ash[y1 * WF + x0], w10);
            if (vy1 & vx1) atomicAdd(&S.Ash[y1 * WF + x1], w11);
        }
        __syncthreads();

        // copy out + SA = sum(Ash)
        const float4* Ash4 = reinterpret_cast<const float4*>(S.Ash);
        float4* A4 = reinterpret_cast<float4*>(g_A) + m * 1024;
        float s = 0.f;
#pragma unroll
        for (int i = 0; i < 2; i++) {
            float4 v = Ash4[i * 512 + tid];
            A4[i * 512 + tid] = v;
            s += v.x + v.y + v.z + v.w;
        }
#pragma unroll
        for (int off = 16; off; off >>= 1)
            s += __shfl_down_sync(0xffffffffu, s, off);
        int warp = tid >> 5, lane = tid & 31;
        if (lane == 0) S.partial[warp] = s;
        __syncthreads();
        if (warp == 0) {
            float t = (lane < 16) ? S.partial[lane] : 0.f;
#pragma unroll
            for (int off = 8; off; off >>= 1)
                t += __shfl_down_sync(0xffffffffu, t, off);
            if (lane == 0) g_SA[m] = t;
        }
    }
}

// ---------------------------------------------------------------------------
// K_reduce: partial u for 8 channels x 3 m's, then Wcomb epilogue:
//   out[m][o] += sum_ch WcT[c0+ch][o] * u_part[m][ch]  (+ bias on ctile 0)
// grid (16 gf, 32 ctiles), block 256.
// ---------------------------------------------------------------------------
__global__ void __launch_bounds__(256) k_reduce(
    const float* __restrict__ feat, const float* __restrict__ b_dc,
    float* __restrict__ out)
{
    int gf = blockIdx.x;            // 0..15 == b*4+g
    int b = gf >> 2, g = gf & 3;
    int m0 = b * 12 + g * 3;

    const float4* A4 = reinterpret_cast<const float4*>(g_A);
    float4 a[3][4];
#pragma unroll
    for (int r = 0; r < 3; r++)
#pragma unroll
        for (int k = 0; k < 4; k++)
            a[r][k] = A4[(m0 + r) * 1024 + k * 256 + threadIdx.x];

    __shared__ float red[8][8][3];
    __shared__ float sacc[3][8];
    int warp = threadIdx.x >> 5;
    int lane = threadIdx.x & 31;

    const float4* F4 = reinterpret_cast<const float4*>(feat)
                     + (size_t)gf * DCH * 1024
                     + (size_t)blockIdx.y * 8 * 1024;

    float4 cur[4], nxt[4];
#pragma unroll
    for (int k = 0; k < 4; k++) cur[k] = F4[k * 256 + threadIdx.x];

#pragma unroll
    for (int ch = 0; ch < 8; ch++) {
        if (ch < 7) {
#pragma unroll
            for (int k = 0; k < 4; k++)
                nxt[k] = F4[(ch + 1) * 1024 + k * 256 + threadIdx.x];
        }
        float acc0 = 0.f, acc1 = 0.f, acc2 = 0.f;
#pragma unroll
        for (int k = 0; k < 4; k++) {
            float4 f = cur[k];
            acc0 += a[0][k].x * f.x + a[0][k].y * f.y + a[0][k].z * f.z + a[0][k].w * f.w;
            acc1 += a[1][k].x * f.x + a[1][k].y * f.y + a[1][k].z * f.z + a[1][k].w * f.w;
            acc2 += a[2][k].x * f.x + a[2][k].y * f.y + a[2][k].z * f.z + a[2][k].w * f.w;
        }
#pragma unroll
        for (int off = 16; off; off >>= 1) {
            acc0 += __shfl_down_sync(0xffffffffu, acc0, off);
            acc1 += __shfl_down_sync(0xffffffffu, acc1, off);
            acc2 += __shfl_down_sync(0xffffffffu, acc2, off);
        }
        if (lane == 0) {
            red[ch][warp][0] = acc0;
            red[ch][warp][1] = acc1;
            red[ch][warp][2] = acc2;
        }
        if (ch < 7) {
#pragma unroll
            for (int k = 0; k < 4; k++) cur[k] = nxt[k];
        }
    }
    __syncthreads();

    if (threadIdx.x < 24) {
        int ch = threadIdx.x / 3;
        int r  = threadIdx.x % 3;
        float s = 0.f;
#pragma unroll
        for (int w = 0; w < 8; w++) s += red[ch][w][r];
        sacc[r][ch] = s;
    }
    __syncthreads();

    // Wcomb epilogue: thread = output channel o
    int o = threadIdx.x;
    int c0 = blockIdx.y * 8;
    float v0 = 0.f, v1 = 0.f, v2 = 0.f;
#pragma unroll
    for (int ch = 0; ch < 8; ch++) {
        float wv = g_WcT[(c0 + ch) * DCH + o];
        v0 += wv * sacc[0][ch];
        v1 += wv * sacc[1][ch];
        v2 += wv * sacc[2][ch];
    }
    if (blockIdx.y == 0) {
        float bc = g_bcomb[o];
        float bd = b_dc[o];
        v0 += g_SA[m0 + 0] * bc + bd;
        v1 += g_SA[m0 + 1] * bc + bd;
        v2 += g_SA[m0 + 2] * bc + bd;
    }
    atomicAdd(&out[(m0 + 0) * DCH + o], v0);
    atomicAdd(&out[(m0 + 1) * DCH + o], v1);
    atomicAdd(&out[(m0 + 2) * DCH + o], v2);
}

// ---------------------------------------------------------------------------
// inputs (metadata order): imgs, i_features, p_motions, W_emb, b_emb, W_dc, b_dc
// output: float32 [4,4,3,256] = 12288 elements
// ---------------------------------------------------------------------------
extern "C" void kernel_launch(void* const* d_in, const int* in_sizes, int n_in,
                              void* d_out, int out_size) {
    const float* i_features = (const float*)d_in[1];
    const float* p_motions  = (const float*)d_in[2];
    const float* W_emb      = (const float*)d_in[3];
    const float* b_emb      = (const float*)d_in[4];
    const float* W_dc       = (const float*)d_in[5];
    const float* b_dc       = (const float*)d_in[6];
    float* out = (float*)d_out;

    cudaFuncSetAttribute(k_front, cudaFuncAttributeMaxDynamicSharedMemorySize, FRONT_SMEM);
    k_front<<<176, 512, FRONT_SMEM>>>(W_emb, b_emb, W_dc, p_motions, out);
    k_reduce<<<dim3(16, 32), 256>>>(i_features, b_dc, out);
}